// round 15
// baseline (speedup 1.0000x reference)
#include <cuda_runtime.h>
#include <cuda_fp16.h>

#define NN 100000
#define EE 1600000
#define EN 1700000   // EE + NN self loops
#define FIN 128
#define HH 64
#define BB 128
#define CC 10
#define NEG_SLOPE 0.2f
#define CAP 96       // padded CSR capacity; deg ~ 1+Poisson(16), P(>96) ~ 0

// ---------------- scratch (device globals; no runtime allocation) ------------
__device__ __half g_hh[NN * HH];   // W-transformed features (fp16, gather side)
__device__ __half g_xh[NN * HH];   // layer output (fp16) -> next layer input
__device__ float g_esrc[NN];
__device__ float g_edst[NN];
__device__ int   g_deg[NN];
__device__ int   g_slot[NN * CAP]; // padded CSR: src ids at [n*CAP, n*CAP+deg)
__device__ float g_ex[NN * CAP];   // per-edge exp(score), same indexing

// ---------------- padded CSR build (no scan; self-loops pre-seeded) ----------

__global__ void csr_init_kernel() {
    int i = blockIdx.x * blockDim.x + threadIdx.x;
    if (i < NN) { g_deg[i] = 1; g_slot[i * CAP] = i; }   // self loop in slot 0
}

// 4 edges per thread via int4 loads (MLP on the atomic+scatter chain).
__global__ void csr_fill_kernel(const int* __restrict__ ei) {
    int i = (blockIdx.x * blockDim.x + threadIdx.x) * 4;
    if (i >= EE) return;
    int4 s4 = *(const int4*)&ei[i];
    int4 d4 = *(const int4*)&ei[EE + i];
    int p0 = atomicAdd(&g_deg[d4.x], 1);
    int p1 = atomicAdd(&g_deg[d4.y], 1);
    int p2 = atomicAdd(&g_deg[d4.z], 1);
    int p3 = atomicAdd(&g_deg[d4.w], 1);
    g_slot[d4.x * CAP + p0] = s4.x;
    g_slot[d4.y * CAP + p1] = s4.y;
    g_slot[d4.z * CAP + p2] = s4.z;
    g_slot[d4.w * CAP + p3] = s4.w;
}

// ---------------- GEMM via mma.sync (tensor pipe) ----------------------------
// h[64 nodes][64 ch] per block; 128 threads = 4 warps, warp -> 16-row strip.
// A (nodes x K) fp16 smem, B = W (64 x K) fp16 smem, 16B XOR swizzle.
#define SWZ(r, kb) ((r) * ROWB + ((kb) ^ (((r) & 7) << 4)))

template <int K_T, bool FROM_XH>
__global__ void gemm_kernel(const float* __restrict__ in,
                            const float* __restrict__ W,
                            const float* __restrict__ a_src,
                            const float* __restrict__ a_dst) {
    constexpr int ROWB = K_T * 2;                 // bytes per smem row
    __shared__ __align__(16) unsigned char As[64 * ROWB];
    __shared__ __align__(16) unsigned char Bs[64 * ROWB];
    int tid = threadIdx.x;
    int lane = tid & 31, wid = tid >> 5;
    int rbase = blockIdx.x * 64;

    // B = W [64][K_T] fp32 -> fp16, swizzled 16B chunks
    for (int ch = tid; ch < 64 * K_T / 8; ch += 128) {
        int n = ch / (K_T / 8);
        int k0 = (ch % (K_T / 8)) * 8;
        const float4* wp = (const float4*)&W[n * K_T + k0];
        float4 f0 = wp[0], f1 = wp[1];
        __half2 hv[4] = { __floats2half2_rn(f0.x, f0.y),
                          __floats2half2_rn(f0.z, f0.w),
                          __floats2half2_rn(f1.x, f1.y),
                          __floats2half2_rn(f1.z, f1.w) };
        *(uint4*)&Bs[SWZ(n, (unsigned)(k0 * 2))] = *(uint4*)hv;
    }
    // A rows rbase..rbase+63
    for (int ch = tid; ch < 64 * K_T / 8; ch += 128) {
        int r = ch / (K_T / 8);
        int k0 = (ch % (K_T / 8)) * 8;
        int node = rbase + r;
        uint4 val = make_uint4(0, 0, 0, 0);
        if (node < NN) {
            if (FROM_XH) {
                val = *(const uint4*)&g_xh[(size_t)node * K_T + k0];
            } else {
                const float4* xp = (const float4*)&in[(size_t)node * K_T + k0];
                float4 f0 = xp[0], f1 = xp[1];
                __half2 hv[4] = { __floats2half2_rn(f0.x, f0.y),
                                  __floats2half2_rn(f0.z, f0.w),
                                  __floats2half2_rn(f1.x, f1.y),
                                  __floats2half2_rn(f1.z, f1.w) };
                val = *(uint4*)hv;
            }
        }
        *(uint4*)&As[SWZ(r, (unsigned)(k0 * 2))] = val;
    }
    __syncthreads();

    int g = lane >> 2, t = lane & 3;
    int r0 = wid * 16;
    float d[8][4];
#pragma unroll
    for (int j = 0; j < 8; j++)
#pragma unroll
        for (int i = 0; i < 4; i++) d[j][i] = 0.f;

#pragma unroll
    for (int kt = 0; kt < K_T / 16; kt++) {
        unsigned kb = kt * 32 + t * 4;
        int ra = r0 + g, rb = ra + 8;
        unsigned a0 = *(const unsigned*)&As[SWZ(ra, kb)];
        unsigned a1 = *(const unsigned*)&As[SWZ(rb, kb)];
        unsigned a2 = *(const unsigned*)&As[SWZ(ra, kb + 16)];
        unsigned a3 = *(const unsigned*)&As[SWZ(rb, kb + 16)];
#pragma unroll
        for (int j = 0; j < 8; j++) {
            int n = j * 8 + g;
            unsigned b0 = *(const unsigned*)&Bs[SWZ(n, kb)];
            unsigned b1 = *(const unsigned*)&Bs[SWZ(n, kb + 16)];
            asm volatile(
                "mma.sync.aligned.m16n8k16.row.col.f32.f16.f16.f32 "
                "{%0,%1,%2,%3}, {%4,%5,%6,%7}, {%8,%9}, {%0,%1,%2,%3};"
                : "+f"(d[j][0]), "+f"(d[j][1]), "+f"(d[j][2]), "+f"(d[j][3])
                : "r"(a0), "r"(a1), "r"(a2), "r"(a3), "r"(b0), "r"(b1));
        }
    }

    // epilogue: h fp16 store + per-node score dots
    int rowA = rbase + r0 + g;
    int rowB = rowA + 8;
    float vsA = 0.f, vdA = 0.f, vsB = 0.f, vdB = 0.f;
#pragma unroll
    for (int j = 0; j < 8; j++) {
        int c = j * 8 + t * 2;
        float2 as2 = *(const float2*)&a_src[c];
        float2 ad2 = *(const float2*)&a_dst[c];
        vsA += d[j][0] * as2.x + d[j][1] * as2.y;
        vdA += d[j][0] * ad2.x + d[j][1] * ad2.y;
        vsB += d[j][2] * as2.x + d[j][3] * as2.y;
        vdB += d[j][2] * ad2.x + d[j][3] * ad2.y;
        if (rowA < NN)
            *(__half2*)&g_hh[(size_t)rowA * HH + c] =
                __floats2half2_rn(d[j][0], d[j][1]);
        if (rowB < NN)
            *(__half2*)&g_hh[(size_t)rowB * HH + c] =
                __floats2half2_rn(d[j][2], d[j][3]);
    }
#pragma unroll
    for (int off = 1; off <= 2; off <<= 1) {
        vsA += __shfl_xor_sync(0xffffffffu, vsA, off);
        vdA += __shfl_xor_sync(0xffffffffu, vdA, off);
        vsB += __shfl_xor_sync(0xffffffffu, vsB, off);
        vdB += __shfl_xor_sync(0xffffffffu, vdB, off);
    }
    if (t == 0) {
        if (rowA < NN) { g_esrc[rowA] = vsA; g_edst[rowA] = vdA; }
        if (rowB < NN) { g_esrc[rowB] = vsB; g_edst[rowB] = vdB; }
    }
}

// ---------------- fused GAT aggregation (warp per dst node, TWO PASS) --------
// pass1: gather scores, leaky-relu, ex=exp(e) stored, warp-sum (no max-shift:
//        scores are O(1), max cancels in alpha).
// pass2: quarter-warp processes CONTIGUOUS edge pairs (j, j+1) stepping by 8:
//        one float2 (ex) + one int2 (slot) load per pair, two uint4 fp16 row
//        gathers, two independent HFMA2 chains -> ~7 issue slots/edge, 8 edges
//        in flight per warp. Tail edge predicated (alpha=0, clamped slot).
template <bool RELU>
__global__ void __launch_bounds__(256)
gat_agg_kernel(const float* __restrict__ bias) {
    int w = (blockIdx.x * blockDim.x + threadIdx.x) >> 5;
    if (w >= NN) return;
    int lane = threadIdx.x & 31;
    int beg = w * CAP;
    int end = beg + g_deg[w];
    float ed = g_edst[w];

    float ssum = 0.f;
    for (int j = beg + lane; j < end; j += 32) {
        float e = g_esrc[g_slot[j]] + ed;
        e = e > 0.f ? e : NEG_SLOPE * e;
        float ex = __expf(e);
        g_ex[j] = ex;
        ssum += ex;
    }
#pragma unroll
    for (int off = 16; off; off >>= 1)
        ssum += __shfl_xor_sync(0xffffffffu, ssum, off);
    float inv = 1.f / ssum;
    __syncwarp();

    int quarter = lane >> 3;
    int oc = (lane & 7) * 8;
    __half2 zero2 = __float2half2_rn(0.f);
    __half2 aA0 = zero2, aA1 = zero2, aA2 = zero2, aA3 = zero2;
    __half2 aB0 = zero2, aB1 = zero2, aB2 = zero2, aB3 = zero2;

    for (int j = beg + 2 * quarter; j < end; j += 8) {
        float2 e2 = *(const float2*)&g_ex[j];        // 8B aligned (beg even)
        int2 ss = *(const int2*)&g_slot[j];
        bool v1 = (j + 1) < end;
        __half2 a0 = __float2half2_rn(e2.x * inv);
        __half2 a1 = __float2half2_rn(v1 ? e2.y * inv : 0.f);
        int s1 = v1 ? ss.y : ss.x;                   // clamp: padding is garbage
        uint4 u0 = *(const uint4*)&g_hh[(ss.x << 6) + oc];
        uint4 u1 = *(const uint4*)&g_hh[(s1 << 6) + oc];
        aA0 = __hfma2(a0, *(__half2*)&u0.x, aA0);
        aA1 = __hfma2(a0, *(__half2*)&u0.y, aA1);
        aA2 = __hfma2(a0, *(__half2*)&u0.z, aA2);
        aA3 = __hfma2(a0, *(__half2*)&u0.w, aA3);
        aB0 = __hfma2(a1, *(__half2*)&u1.x, aB0);
        aB1 = __hfma2(a1, *(__half2*)&u1.y, aB1);
        aB2 = __hfma2(a1, *(__half2*)&u1.z, aB2);
        aB3 = __hfma2(a1, *(__half2*)&u1.w, aB3);
    }
    // to fp32, merge A/B chains, reduce across the 4 quarters
    float2 p0 = __half22float2(aA0), q0 = __half22float2(aB0);
    float2 p1 = __half22float2(aA1), q1 = __half22float2(aB1);
    float2 p2 = __half22float2(aA2), q2 = __half22float2(aB2);
    float2 p3 = __half22float2(aA3), q3 = __half22float2(aB3);
    float acc[8] = {p0.x + q0.x, p0.y + q0.y, p1.x + q1.x, p1.y + q1.y,
                    p2.x + q2.x, p2.y + q2.y, p3.x + q3.x, p3.y + q3.y};
#pragma unroll
    for (int i = 0; i < 8; i++) {
        acc[i] += __shfl_xor_sync(0xffffffffu, acc[i], 8);
        acc[i] += __shfl_xor_sync(0xffffffffu, acc[i], 16);
    }
    if (quarter == 0) {
        __half2 hv[4];
#pragma unroll
        for (int p = 0; p < 4; p++) {
            float v0 = acc[2 * p] + bias[oc + 2 * p];
            float v1 = acc[2 * p + 1] + bias[oc + 2 * p + 1];
            if (RELU) { v0 = fmaxf(v0, 0.f); v1 = fmaxf(v1, 0.f); }
            hv[p] = __floats2half2_rn(v0, v1);
        }
        *(uint4*)&g_xh[(w << 6) + oc] = *(uint4*)hv;
    }
}

// ---------------- fused pool + linear (block per graph, no atomics) ----------

__global__ void pool_linear_kernel(const int* __restrict__ batch,
                                   const float* __restrict__ Wlin,
                                   const float* __restrict__ blin,
                                   float* __restrict__ out) {
    int b = blockIdx.x;
    int lo = 0, hi = NN;
    while (lo < hi) { int mid = (lo + hi) >> 1;
                      if (batch[mid] < b) lo = mid + 1; else hi = mid; }
    int start = lo;
    hi = NN;
    while (lo < hi) { int mid = (lo + hi) >> 1;
                      if (batch[mid] < b + 1) lo = mid + 1; else hi = mid; }
    int end = lo;

    int c = threadIdx.x & 63, r = threadIdx.x >> 6;   // 4 rows of 64
    float s = 0.f;
    for (int n = start + r; n < end; n += 4)
        s += __half2float(g_xh[(size_t)n * HH + c]);
    __shared__ float sm[4][HH];
    __shared__ float pooled[HH];
    sm[r][c] = s;
    __syncthreads();
    if (threadIdx.x < HH) {
        float tot = sm[0][c] + sm[1][c] + sm[2][c] + sm[3][c];
        pooled[c] = tot / fmaxf((float)(end - start), 1.f);
    }
    __syncthreads();
    if (threadIdx.x < CC) {
        int j = threadIdx.x;
        float acc = blin[j];
#pragma unroll
        for (int k = 0; k < HH; k++)
            acc += pooled[k] * Wlin[j * HH + k];
        out[b * CC + j] = acc;
    }
}

// ---------------- launch -----------------------------------------------------

extern "C" void kernel_launch(void* const* d_in, const int* in_sizes, int n_in,
                              void* d_out, int out_size) {
    const float* x     = (const float*)d_in[0];
    const int*   ei    = (const int*)d_in[1];
    const int*   batch = (const int*)d_in[2];
    const float* W1 = (const float*)d_in[3];
    const float* as1 = (const float*)d_in[4];
    const float* ad1 = (const float*)d_in[5];
    const float* b1 = (const float*)d_in[6];
    const float* W2 = (const float*)d_in[7];
    const float* as2 = (const float*)d_in[8];
    const float* ad2 = (const float*)d_in[9];
    const float* b2 = (const float*)d_in[10];
    const float* W3 = (const float*)d_in[11];
    const float* as3 = (const float*)d_in[12];
    const float* ad3 = (const float*)d_in[13];
    const float* b3 = (const float*)d_in[14];
    const float* Wlin = (const float*)d_in[15];
    const float* blin = (const float*)d_in[16];

    cudaStream_t main_s = 0;
    cudaStream_t side;
    cudaStreamCreateWithFlags(&side, cudaStreamNonBlocking);
    cudaEvent_t evA, evB;
    cudaEventCreateWithFlags(&evA, cudaEventDisableTiming);
    cudaEventCreateWithFlags(&evB, cudaEventDisableTiming);

    // Fork: padded CSR build on `side`, concurrent with layer-1 GEMM on main.
    cudaEventRecord(evA, main_s);
    cudaStreamWaitEvent(side, evA, 0);
    csr_init_kernel<<<(NN + 255) / 256, 256, 0, side>>>();
    csr_fill_kernel<<<(EE / 4 + 255) / 256, 256, 0, side>>>(ei);
    cudaEventRecord(evB, side);

    int gblocks = (NN + 63) / 64;
    gemm_kernel<FIN, false><<<gblocks, 128, 0, main_s>>>(x, W1, as1, ad1);

    // Join: aggregation needs both the CSR and the layer-1 GEMM results.
    cudaStreamWaitEvent(main_s, evB, 0);

    int ablocks = (NN * 32 + 255) / 256;
    gat_agg_kernel<true><<<ablocks, 256, 0, main_s>>>(b1);

    gemm_kernel<HH, true><<<gblocks, 128, 0, main_s>>>(nullptr, W2, as2, ad2);
    gat_agg_kernel<true><<<ablocks, 256, 0, main_s>>>(b2);

    gemm_kernel<HH, true><<<gblocks, 128, 0, main_s>>>(nullptr, W3, as3, ad3);
    gat_agg_kernel<false><<<ablocks, 256, 0, main_s>>>(b3);

    pool_linear_kernel<<<BB, 256, 0, main_s>>>(batch, Wlin, blin,
                                               (float*)d_out);

    cudaEventDestroy(evA);
    cudaEventDestroy(evB);
    cudaStreamDestroy(side);
}

// round 16
// speedup vs baseline: 1.5896x; 1.5896x over previous
#include <cuda_runtime.h>
#include <cuda_fp16.h>

#define NN 100000
#define EE 1600000
#define EN 1700000   // EE + NN self loops
#define FIN 128
#define HH 64
#define BB 128
#define CC 10
#define NEG_SLOPE 0.2f
#define CAP 96       // padded CSR capacity; deg ~ 1+Poisson(16), P(>96) ~ 0

// ---------------- scratch (device globals; no runtime allocation) ------------
__device__ __half g_hh[NN * HH];   // W-transformed features (fp16, gather side)
__device__ __half g_xh[NN * HH];   // layer output (fp16) -> next layer input
__device__ float g_esrc[NN];
__device__ float g_edst[NN];
__device__ int   g_deg[NN];
__device__ int   g_slot[NN * CAP]; // padded CSR: src ids at [n*CAP, n*CAP+deg)
__device__ float g_ex[NN * CAP];   // per-edge exp(score), same indexing

// ---------------- padded CSR build (no scan; self-loops pre-seeded) ----------

__global__ void csr_init_kernel() {
    int i = blockIdx.x * blockDim.x + threadIdx.x;
    if (i < NN) { g_deg[i] = 1; g_slot[i * CAP] = i; }   // self loop in slot 0
}

// 4 edges per thread via int4 loads (MLP on the atomic+scatter chain).
__global__ void csr_fill_kernel(const int* __restrict__ ei) {
    int i = (blockIdx.x * blockDim.x + threadIdx.x) * 4;
    if (i >= EE) return;
    int4 s4 = *(const int4*)&ei[i];
    int4 d4 = *(const int4*)&ei[EE + i];
    int p0 = atomicAdd(&g_deg[d4.x], 1);
    int p1 = atomicAdd(&g_deg[d4.y], 1);
    int p2 = atomicAdd(&g_deg[d4.z], 1);
    int p3 = atomicAdd(&g_deg[d4.w], 1);
    g_slot[d4.x * CAP + p0] = s4.x;
    g_slot[d4.y * CAP + p1] = s4.y;
    g_slot[d4.z * CAP + p2] = s4.z;
    g_slot[d4.w * CAP + p3] = s4.w;
}

// ---------------- GEMM via mma.sync (tensor pipe) ----------------------------
// h[64 nodes][64 ch] per block; 128 threads = 4 warps, warp -> 16-row strip.
// A (nodes x K) fp16 smem, B = W (64 x K) fp16 smem, 16B XOR swizzle.
#define SWZ(r, kb) ((r) * ROWB + ((kb) ^ (((r) & 7) << 4)))

template <int K_T, bool FROM_XH>
__global__ void gemm_kernel(const float* __restrict__ in,
                            const float* __restrict__ W,
                            const float* __restrict__ a_src,
                            const float* __restrict__ a_dst) {
    constexpr int ROWB = K_T * 2;                 // bytes per smem row
    __shared__ __align__(16) unsigned char As[64 * ROWB];
    __shared__ __align__(16) unsigned char Bs[64 * ROWB];
    int tid = threadIdx.x;
    int lane = tid & 31, wid = tid >> 5;
    int rbase = blockIdx.x * 64;

    // B = W [64][K_T] fp32 -> fp16, swizzled 16B chunks
    for (int ch = tid; ch < 64 * K_T / 8; ch += 128) {
        int n = ch / (K_T / 8);
        int k0 = (ch % (K_T / 8)) * 8;
        const float4* wp = (const float4*)&W[n * K_T + k0];
        float4 f0 = wp[0], f1 = wp[1];
        __half2 hv[4] = { __floats2half2_rn(f0.x, f0.y),
                          __floats2half2_rn(f0.z, f0.w),
                          __floats2half2_rn(f1.x, f1.y),
                          __floats2half2_rn(f1.z, f1.w) };
        *(uint4*)&Bs[SWZ(n, (unsigned)(k0 * 2))] = *(uint4*)hv;
    }
    // A rows rbase..rbase+63
    for (int ch = tid; ch < 64 * K_T / 8; ch += 128) {
        int r = ch / (K_T / 8);
        int k0 = (ch % (K_T / 8)) * 8;
        int node = rbase + r;
        uint4 val = make_uint4(0, 0, 0, 0);
        if (node < NN) {
            if (FROM_XH) {
                val = *(const uint4*)&g_xh[(size_t)node * K_T + k0];
            } else {
                const float4* xp = (const float4*)&in[(size_t)node * K_T + k0];
                float4 f0 = xp[0], f1 = xp[1];
                __half2 hv[4] = { __floats2half2_rn(f0.x, f0.y),
                                  __floats2half2_rn(f0.z, f0.w),
                                  __floats2half2_rn(f1.x, f1.y),
                                  __floats2half2_rn(f1.z, f1.w) };
                val = *(uint4*)hv;
            }
        }
        *(uint4*)&As[SWZ(r, (unsigned)(k0 * 2))] = val;
    }
    __syncthreads();

    int g = lane >> 2, t = lane & 3;
    int r0 = wid * 16;
    float d[8][4];
#pragma unroll
    for (int j = 0; j < 8; j++)
#pragma unroll
        for (int i = 0; i < 4; i++) d[j][i] = 0.f;

#pragma unroll
    for (int kt = 0; kt < K_T / 16; kt++) {
        unsigned kb = kt * 32 + t * 4;
        int ra = r0 + g, rb = ra + 8;
        unsigned a0 = *(const unsigned*)&As[SWZ(ra, kb)];
        unsigned a1 = *(const unsigned*)&As[SWZ(rb, kb)];
        unsigned a2 = *(const unsigned*)&As[SWZ(ra, kb + 16)];
        unsigned a3 = *(const unsigned*)&As[SWZ(rb, kb + 16)];
#pragma unroll
        for (int j = 0; j < 8; j++) {
            int n = j * 8 + g;
            unsigned b0 = *(const unsigned*)&Bs[SWZ(n, kb)];
            unsigned b1 = *(const unsigned*)&Bs[SWZ(n, kb + 16)];
            asm volatile(
                "mma.sync.aligned.m16n8k16.row.col.f32.f16.f16.f32 "
                "{%0,%1,%2,%3}, {%4,%5,%6,%7}, {%8,%9}, {%0,%1,%2,%3};"
                : "+f"(d[j][0]), "+f"(d[j][1]), "+f"(d[j][2]), "+f"(d[j][3])
                : "r"(a0), "r"(a1), "r"(a2), "r"(a3), "r"(b0), "r"(b1));
        }
    }

    // epilogue: h fp16 store + per-node score dots
    int rowA = rbase + r0 + g;
    int rowB = rowA + 8;
    float vsA = 0.f, vdA = 0.f, vsB = 0.f, vdB = 0.f;
#pragma unroll
    for (int j = 0; j < 8; j++) {
        int c = j * 8 + t * 2;
        float2 as2 = *(const float2*)&a_src[c];
        float2 ad2 = *(const float2*)&a_dst[c];
        vsA += d[j][0] * as2.x + d[j][1] * as2.y;
        vdA += d[j][0] * ad2.x + d[j][1] * ad2.y;
        vsB += d[j][2] * as2.x + d[j][3] * as2.y;
        vdB += d[j][2] * ad2.x + d[j][3] * ad2.y;
        if (rowA < NN)
            *(__half2*)&g_hh[(size_t)rowA * HH + c] =
                __floats2half2_rn(d[j][0], d[j][1]);
        if (rowB < NN)
            *(__half2*)&g_hh[(size_t)rowB * HH + c] =
                __floats2half2_rn(d[j][2], d[j][3]);
    }
#pragma unroll
    for (int off = 1; off <= 2; off <<= 1) {
        vsA += __shfl_xor_sync(0xffffffffu, vsA, off);
        vdA += __shfl_xor_sync(0xffffffffu, vdA, off);
        vsB += __shfl_xor_sync(0xffffffffu, vsB, off);
        vdB += __shfl_xor_sync(0xffffffffu, vdB, off);
    }
    if (t == 0) {
        if (rowA < NN) { g_esrc[rowA] = vsA; g_edst[rowA] = vdA; }
        if (rowB < NN) { g_esrc[rowB] = vsB; g_edst[rowB] = vdB; }
    }
}

// ---------------- fused GAT aggregation (warp per dst node, TWO PASS) --------
// pass1: gather scores, leaky-relu, ex=exp(e) stored, warp-sum (no max-shift:
//        scores are O(1), max cancels in alpha).
// pass2: quarter-warp per edge, LDG.128 fp16 rows, HFMA2 half2 accumulation
//        (R14 form: 32 regs, occ ~83%; R15's pairwise unroll raised regs to 38,
//        dropped occ to 61% and regressed 75% — do not re-unroll).
template <bool RELU>
__global__ void __launch_bounds__(256)
gat_agg_kernel(const float* __restrict__ bias) {
    int w = (blockIdx.x * blockDim.x + threadIdx.x) >> 5;
    if (w >= NN) return;
    int lane = threadIdx.x & 31;
    int beg = w * CAP;
    int end = beg + g_deg[w];
    float ed = g_edst[w];

    float ssum = 0.f;
    for (int j = beg + lane; j < end; j += 32) {
        float e = g_esrc[g_slot[j]] + ed;
        e = e > 0.f ? e : NEG_SLOPE * e;
        float ex = __expf(e);
        g_ex[j] = ex;
        ssum += ex;
    }
#pragma unroll
    for (int off = 16; off; off >>= 1)
        ssum += __shfl_xor_sync(0xffffffffu, ssum, off);
    float inv = 1.f / ssum;
    __syncwarp();

    int quarter = lane >> 3;
    int oc = (lane & 7) * 8;
    __half2 acch0 = __float2half2_rn(0.f), acch1 = acch0,
            acch2 = acch0, acch3 = acch0;

    for (int j = beg + quarter; j < end; j += 4) {
        __half2 a2 = __float2half2_rn(g_ex[j] * inv);  // alpha, both halves
        int sN = g_slot[j];
        uint4 u = *(const uint4*)&g_hh[(sN << 6) + oc];
        acch0 = __hfma2(a2, *(__half2*)&u.x, acch0);
        acch1 = __hfma2(a2, *(__half2*)&u.y, acch1);
        acch2 = __hfma2(a2, *(__half2*)&u.z, acch2);
        acch3 = __hfma2(a2, *(__half2*)&u.w, acch3);
    }
    // to fp32, reduce across the 4 quarters
    float2 p0 = __half22float2(acch0);
    float2 p1 = __half22float2(acch1);
    float2 p2 = __half22float2(acch2);
    float2 p3 = __half22float2(acch3);
    float acc[8] = {p0.x, p0.y, p1.x, p1.y, p2.x, p2.y, p3.x, p3.y};
#pragma unroll
    for (int i = 0; i < 8; i++) {
        acc[i] += __shfl_xor_sync(0xffffffffu, acc[i], 8);
        acc[i] += __shfl_xor_sync(0xffffffffu, acc[i], 16);
    }
    if (quarter == 0) {
        __half2 hv[4];
#pragma unroll
        for (int p = 0; p < 4; p++) {
            float v0 = acc[2 * p] + bias[oc + 2 * p];
            float v1 = acc[2 * p + 1] + bias[oc + 2 * p + 1];
            if (RELU) { v0 = fmaxf(v0, 0.f); v1 = fmaxf(v1, 0.f); }
            hv[p] = __floats2half2_rn(v0, v1);
        }
        *(uint4*)&g_xh[(w << 6) + oc] = *(uint4*)hv;
    }
}

// ---------------- fused pool + linear (block per graph, no atomics) ----------

__global__ void pool_linear_kernel(const int* __restrict__ batch,
                                   const float* __restrict__ Wlin,
                                   const float* __restrict__ blin,
                                   float* __restrict__ out) {
    int b = blockIdx.x;
    int lo = 0, hi = NN;
    while (lo < hi) { int mid = (lo + hi) >> 1;
                      if (batch[mid] < b) lo = mid + 1; else hi = mid; }
    int start = lo;
    hi = NN;
    while (lo < hi) { int mid = (lo + hi) >> 1;
                      if (batch[mid] < b + 1) lo = mid + 1; else hi = mid; }
    int end = lo;

    int c = threadIdx.x & 63, r = threadIdx.x >> 6;   // 4 rows of 64
    float s = 0.f;
    for (int n = start + r; n < end; n += 4)
        s += __half2float(g_xh[(size_t)n * HH + c]);
    __shared__ float sm[4][HH];
    __shared__ float pooled[HH];
    sm[r][c] = s;
    __syncthreads();
    if (threadIdx.x < HH) {
        float tot = sm[0][c] + sm[1][c] + sm[2][c] + sm[3][c];
        pooled[c] = tot / fmaxf((float)(end - start), 1.f);
    }
    __syncthreads();
    if (threadIdx.x < CC) {
        int j = threadIdx.x;
        float acc = blin[j];
#pragma unroll
        for (int k = 0; k < HH; k++)
            acc += pooled[k] * Wlin[j * HH + k];
        out[b * CC + j] = acc;
    }
}

// ---------------- launch -----------------------------------------------------

extern "C" void kernel_launch(void* const* d_in, const int* in_sizes, int n_in,
                              void* d_out, int out_size) {
    const float* x     = (const float*)d_in[0];
    const int*   ei    = (const int*)d_in[1];
    const int*   batch = (const int*)d_in[2];
    const float* W1 = (const float*)d_in[3];
    const float* as1 = (const float*)d_in[4];
    const float* ad1 = (const float*)d_in[5];
    const float* b1 = (const float*)d_in[6];
    const float* W2 = (const float*)d_in[7];
    const float* as2 = (const float*)d_in[8];
    const float* ad2 = (const float*)d_in[9];
    const float* b2 = (const float*)d_in[10];
    const float* W3 = (const float*)d_in[11];
    const float* as3 = (const float*)d_in[12];
    const float* ad3 = (const float*)d_in[13];
    const float* b3 = (const float*)d_in[14];
    const float* Wlin = (const float*)d_in[15];
    const float* blin = (const float*)d_in[16];

    cudaStream_t main_s = 0;
    cudaStream_t side;
    cudaStreamCreateWithFlags(&side, cudaStreamNonBlocking);
    cudaEvent_t evA, evB;
    cudaEventCreateWithFlags(&evA, cudaEventDisableTiming);
    cudaEventCreateWithFlags(&evB, cudaEventDisableTiming);

    // Fork: padded CSR build on `side`, concurrent with layer-1 GEMM on main.
    cudaEventRecord(evA, main_s);
    cudaStreamWaitEvent(side, evA, 0);
    csr_init_kernel<<<(NN + 255) / 256, 256, 0, side>>>();
    csr_fill_kernel<<<(EE / 4 + 255) / 256, 256, 0, side>>>(ei);
    cudaEventRecord(evB, side);

    int gblocks = (NN + 63) / 64;
    gemm_kernel<FIN, false><<<gblocks, 128, 0, main_s>>>(x, W1, as1, ad1);

    // Join: aggregation needs both the CSR and the layer-1 GEMM results.
    cudaStreamWaitEvent(main_s, evB, 0);

    int ablocks = (NN * 32 + 255) / 256;
    gat_agg_kernel<true><<<ablocks, 256, 0, main_s>>>(b1);

    gemm_kernel<HH, true><<<gblocks, 128, 0, main_s>>>(nullptr, W2, as2, ad2);
    gat_agg_kernel<true><<<ablocks, 256, 0, main_s>>>(b2);

    gemm_kernel<HH, true><<<gblocks, 128, 0, main_s>>>(nullptr, W3, as3, ad3);
    gat_agg_kernel<false><<<ablocks, 256, 0, main_s>>>(b3);

    pool_linear_kernel<<<BB, 256, 0, main_s>>>(batch, Wlin, blin,
                                               (float*)d_out);

    cudaEventDestroy(evA);
    cudaEventDestroy(evB);
    cudaStreamDestroy(side);
}